// round 12
// baseline (speedup 1.0000x reference)
#include <cuda_runtime.h>
#include <cuda_bf16.h>
#include <cuda_fp16.h>
#include <cstdint>

// ---------------------------------------------------------------------------
// Problem dims
// ---------------------------------------------------------------------------
static constexpr int K_DIM = 4096;   // in_features
static constexpr int N_DIM = 4096;   // out_features
static constexpr int M_DIM = 16384;  // B*S

// Canonical bf16 buffers (GEMM inputs), independent of input storage dtypes.
__device__ __nv_bfloat16 g_w[(size_t)N_DIM * K_DIM];   // 32 MB  [N, K]
__device__ __nv_bfloat16 g_x[(size_t)M_DIM * K_DIM];   // 128 MB [M, K]

// Runtime dtype-detection flags (deterministic given fixed inputs).
__device__ int g_q_is_i8;    // 1 if q stored as int8,  0 if int32
__device__ int g_sc_is_f16;  // 1 if scale stored fp16, 0 if fp32
__device__ int g_x_is_f32;   // 1 if x stored fp32,     0 if bf16

// ---------------------------------------------------------------------------
// Probe: detect storage dtypes by bit-pattern inspection (deterministic).
// ---------------------------------------------------------------------------
__global__ void probe_kernel(const int* __restrict__ q, const float* __restrict__ sc,
                             const unsigned* __restrict__ x) {
    __shared__ int bad_q, ok_s, ok_x;
    int tid = threadIdx.x;
    if (tid == 0) { bad_q = 0; ok_s = 0; ok_x = 0; }
    __syncthreads();

    int bq = 0;
#pragma unroll
    for (int j = 0; j < 4; j++) {
        int v = q[tid * 4 + j];
        if (v > 31 || v < -31) bq++;
    }

    float s = sc[tid];
    int os = (s > 1e-5f && s < 1.0f) ? 1 : 0;

    int ox = 0;
#pragma unroll
    for (int j = 0; j < 16; j++) {
        unsigned w = x[(size_t)(tid * 16 + j) * 131];
        unsigned e = (w >> 7) & 0xFF;
        if (e >= 105 && e <= 132) ox++;
    }

    atomicAdd(&bad_q, bq);
    atomicAdd(&ok_s, os);
    atomicAdd(&ok_x, ox);
    __syncthreads();
    if (tid == 0) {
        g_q_is_i8   = (bad_q > 0) ? 1 : 0;
        g_sc_is_f16 = (ok_s < 200) ? 1 : 0;
        g_x_is_f32  = (ok_x < 2048) ? 1 : 0;
    }
}

// ---------------------------------------------------------------------------
// Dequant: w[n,k] = bf16(float(q[n,k]) * float(scale[n]))  (reference rounding)
// ---------------------------------------------------------------------------
__global__ void dequant_kernel(const void* __restrict__ qv, const void* __restrict__ scv) {
    size_t idx = ((size_t)blockIdx.x * blockDim.x + threadIdx.x) * 8;
    int row = (int)(idx >> 12);  // /4096
    float s;
    if (g_sc_is_f16) s = __half2float(((const __half*)scv)[row]);
    else             s = ((const float*)scv)[row];

    int v[8];
    if (g_q_is_i8) {
        int2 w = *reinterpret_cast<const int2*>((const int8_t*)qv + idx);
        const int8_t* b = reinterpret_cast<const int8_t*>(&w);
#pragma unroll
        for (int i = 0; i < 8; i++) v[i] = (int)b[i];
    } else {
        const int4* p = reinterpret_cast<const int4*>((const int*)qv + idx);
        int4 a = p[0], b2 = p[1];
        v[0] = a.x; v[1] = a.y; v[2] = a.z; v[3] = a.w;
        v[4] = b2.x; v[5] = b2.y; v[6] = b2.z; v[7] = b2.w;
    }
    __nv_bfloat16 o[8];
#pragma unroll
    for (int i = 0; i < 8; i++) o[i] = __float2bfloat16(s * (float)v[i]);
    *reinterpret_cast<uint4*>(&g_w[idx]) = *reinterpret_cast<const uint4*>(o);
}

// ---------------------------------------------------------------------------
// Canonicalize x to bf16 (used only when x arrives fp32-widened).
// ---------------------------------------------------------------------------
__global__ void convert_x_kernel(const void* __restrict__ xv) {
    size_t idx = ((size_t)blockIdx.x * blockDim.x + threadIdx.x) * 8;
    if (g_x_is_f32) {
        const float4* p = reinterpret_cast<const float4*>((const float*)xv + idx);
        float4 a = p[0], b = p[1];
        __nv_bfloat16 o[8];
        o[0] = __float2bfloat16(a.x); o[1] = __float2bfloat16(a.y);
        o[2] = __float2bfloat16(a.z); o[3] = __float2bfloat16(a.w);
        o[4] = __float2bfloat16(b.x); o[5] = __float2bfloat16(b.y);
        o[6] = __float2bfloat16(b.z); o[7] = __float2bfloat16(b.w);
        *reinterpret_cast<uint4*>(&g_x[idx]) = *reinterpret_cast<const uint4*>(o);
    }
}

// ===========================================================================
// Tensor-core GEMM via mma.sync. CTA 256x128x32, 8 warps (4m x 2n), warp
// tile 64x64 (MMA:LDSM = 4:1). 4-stage cp.async, ONE barrier per K-step,
// loads issued before compute. 80B-padded rows -> conflict-free ldmatrix.
// Output: f32(bf16(f32_accum)) stored as FLOAT32.
// ===========================================================================
static constexpr int FB_BM = 256;
static constexpr int FB_BN = 128;
static constexpr int FB_BK = 32;
static constexpr int FB_KT = K_DIM / FB_BK;                   // 128
static constexpr int FB_STRIDE = 40;                          // elems per row (80B)
static constexpr int FB_A_BYTES = FB_BM * FB_STRIDE * 2;      // 20480
static constexpr int FB_B_BYTES = FB_BN * FB_STRIDE * 2;      // 10240
static constexpr int FB_STAGE_BYTES = FB_A_BYTES + FB_B_BYTES;// 30720
static constexpr int FB_STAGES = 4;
static constexpr int FB_SMEM = FB_STAGES * FB_STAGE_BYTES;    // 122880 -> 1 CTA/SM

__device__ __forceinline__ uint32_t smem_to_u32(const void* p) {
    uint32_t a;
    asm("{ .reg .u64 t; cvta.to.shared.u64 t, %1; cvt.u32.u64 %0, t; }" : "=r"(a) : "l"(p));
    return a;
}

#define CP_ASYNC_16(smem, gmem) \
    asm volatile("cp.async.cg.shared.global [%0], [%1], 16;" :: "r"((uint32_t)(smem)), "l"(gmem) : "memory")
#define CP_COMMIT() asm volatile("cp.async.commit_group;" ::: "memory")
#define CP_WAIT_GROUP(n) asm volatile("cp.async.wait_group %0;" :: "n"(n) : "memory")

#define LDMATRIX_X4(r0, r1, r2, r3, addr) \
    asm volatile("ldmatrix.sync.aligned.m8n8.x4.shared.b16 {%0,%1,%2,%3}, [%4];" \
        : "=r"(r0), "=r"(r1), "=r"(r2), "=r"(r3) : "r"(addr))

#define MMA_16816_BF16(d, a, b) \
    asm volatile("mma.sync.aligned.m16n8k16.row.col.f32.bf16.bf16.f32 " \
        "{%0,%1,%2,%3}, {%4,%5,%6,%7}, {%8,%9}, {%0,%1,%2,%3};" \
        : "+f"((d)[0]), "+f"((d)[1]), "+f"((d)[2]), "+f"((d)[3]) \
        : "r"((a)[0]), "r"((a)[1]), "r"((a)[2]), "r"((a)[3]), "r"((b)[0]), "r"((b)[1]))

__device__ __forceinline__ void fb_load_stage(const __nv_bfloat16* __restrict__ xsrc,
                                              int m0, int n0, int k0,
                                              uint32_t stage_smem, int tid) {
    // A: 256 rows x 4 chunks(16B) = 1024; 256 threads -> 4 each.
    uint32_t a_base = stage_smem;
#pragma unroll
    for (int i = 0; i < 4; i++) {
        int idx = tid + i * 256;
        int r = idx >> 2, c = idx & 3;
        uint32_t off = (uint32_t)(r * (FB_STRIDE * 2) + c * 16);
        const void* g = (const void*)(xsrc + (size_t)(m0 + r) * K_DIM + k0 + c * 8);
        CP_ASYNC_16(a_base + off, g);
    }
    // B: 128 rows x 4 chunks = 512; 2 each.
    uint32_t b_base = stage_smem + FB_A_BYTES;
#pragma unroll
    for (int i = 0; i < 2; i++) {
        int idx = tid + i * 256;
        int r = idx >> 2, c = idx & 3;
        uint32_t off = (uint32_t)(r * (FB_STRIDE * 2) + c * 16);
        const void* g = (const void*)(g_w + (size_t)(n0 + r) * K_DIM + k0 + c * 8);
        CP_ASYNC_16(b_base + off, g);
    }
}

__global__ void __launch_bounds__(256, 1)
gemm_mma(float* __restrict__ out, const __nv_bfloat16* __restrict__ x_raw) {
    extern __shared__ char smem_raw[];
    uint32_t smem_base = smem_to_u32(smem_raw);

    int tid = threadIdx.x;
    int wid = tid >> 5;
    int lid = tid & 31;
    int warp_m = wid & 3;     // 4 warps along M, stride 64
    int warp_n = wid >> 2;    // 2 warps along N, stride 64

    int n_tile = blockIdx.x & 31;   // n fastest: W stays L2-hot
    int m_tile = blockIdx.x >> 5;   // 64 m-tiles
    int m0 = m_tile * FB_BM;
    int n0 = n_tile * FB_BN;

    const __nv_bfloat16* xsrc = g_x_is_f32 ? g_x : x_raw;

    float acc[4][8][4];             // 4 m-subtiles x 8 n-subtiles x 4
#pragma unroll
    for (int t = 0; t < 4; t++)
#pragma unroll
        for (int j = 0; j < 8; j++)
#pragma unroll
            for (int e = 0; e < 4; e++) acc[t][j][e] = 0.0f;

    fb_load_stage(xsrc, m0, n0, 0 * FB_BK, smem_base + 0 * FB_STAGE_BYTES, tid);
    CP_COMMIT();
    fb_load_stage(xsrc, m0, n0, 1 * FB_BK, smem_base + 1 * FB_STAGE_BYTES, tid);
    CP_COMMIT();
    fb_load_stage(xsrc, m0, n0, 2 * FB_BK, smem_base + 2 * FB_STAGE_BYTES, tid);
    CP_COMMIT();

    int lr = lid & 7;
    int lg = lid >> 3;

    for (int kt = 0; kt < FB_KT; ++kt) {
        CP_WAIT_GROUP(2);
        __syncthreads();

        // Issue next loads FIRST so they overlap the whole compute phase.
        if (kt + 3 < FB_KT) {
            fb_load_stage(xsrc, m0, n0, (kt + 3) * FB_BK,
                          smem_base + (uint32_t)((kt + 3) & 3) * FB_STAGE_BYTES, tid);
        }
        CP_COMMIT();

        uint32_t stage = smem_base + (uint32_t)(kt & 3) * FB_STAGE_BYTES;
        uint32_t a_base = stage;
        uint32_t b_base = stage + FB_A_BYTES;

#pragma unroll
        for (int ki = 0; ki < 2; ki++) {
            uint32_t a_frag[4][4];
#pragma unroll
            for (int t = 0; t < 4; t++) {
                int row = warp_m * 64 + t * 16 + (lg & 1) * 8 + lr;
                int col = ki * 16 + (lg >> 1) * 8;
                uint32_t addr = a_base + (uint32_t)(row * (FB_STRIDE * 2) + col * 2);
                LDMATRIX_X4(a_frag[t][0], a_frag[t][1], a_frag[t][2], a_frag[t][3], addr);
            }
            uint32_t b_frag[8][2];
#pragma unroll
            for (int j2 = 0; j2 < 4; j2++) {
                int nrow = warp_n * 64 + (j2 * 2 + (lg >> 1)) * 8 + lr;
                int kcol = ki * 16 + (lg & 1) * 8;
                uint32_t addr = b_base + (uint32_t)(nrow * (FB_STRIDE * 2) + kcol * 2);
                LDMATRIX_X4(b_frag[2 * j2][0], b_frag[2 * j2][1],
                            b_frag[2 * j2 + 1][0], b_frag[2 * j2 + 1][1], addr);
            }
#pragma unroll
            for (int t = 0; t < 4; t++)
#pragma unroll
                for (int j = 0; j < 8; j++)
                    MMA_16816_BF16(acc[t][j], a_frag[t], b_frag[j]);
        }
        // Buffer (kt)&3 is only rewritten at kt+4 whose top sync orders it.
    }

    // Epilogue: bf16-round (reference einsum output), widen, store FP32.
    int qr = lid >> 2;
    int qc = lid & 3;
#pragma unroll
    for (int t = 0; t < 4; t++) {
#pragma unroll
        for (int j = 0; j < 8; j++) {
            size_t row0 = (size_t)m0 + warp_m * 64 + t * 16 + qr;
            size_t col = (size_t)n0 + warp_n * 64 + j * 8 + qc * 2;
            float2 v0, v1;
            v0.x = __bfloat162float(__float2bfloat16(acc[t][j][0]));
            v0.y = __bfloat162float(__float2bfloat16(acc[t][j][1]));
            v1.x = __bfloat162float(__float2bfloat16(acc[t][j][2]));
            v1.y = __bfloat162float(__float2bfloat16(acc[t][j][3]));
            *reinterpret_cast<float2*>(out + row0 * N_DIM + col) = v0;
            *reinterpret_cast<float2*>(out + (row0 + 8) * N_DIM + col) = v1;
        }
    }
}

// ---------------------------------------------------------------------------
// Launch. Inputs routed by element count; dtypes detected on-device.
// ---------------------------------------------------------------------------
extern "C" void kernel_launch(void* const* d_in, const int* in_sizes, int n_in,
                              void* d_out, int out_size) {
    const void* x = nullptr;
    const void* q = nullptr;
    const void* scale = nullptr;
    for (int i = 0; i < n_in; i++) {
        if (in_sizes[i] == M_DIM * K_DIM) x = d_in[i];
        else if (in_sizes[i] == N_DIM * K_DIM) q = d_in[i];
        else if (in_sizes[i] == N_DIM) scale = d_in[i];
    }
    float* out = (float*)d_out;

    cudaFuncSetAttribute(gemm_mma, cudaFuncAttributeMaxDynamicSharedMemorySize, FB_SMEM);

    probe_kernel<<<1, 256>>>((const int*)q, (const float*)scale, (const unsigned*)x);

    dequant_kernel<<<8192, 256>>>(q, scale);       // 16.7M / (256*8)
    convert_x_kernel<<<32768, 256>>>(x);           // no-op if x already bf16

    int grid = (M_DIM / FB_BM) * (N_DIM / FB_BN);  // 64 * 32 = 2048
    gemm_mma<<<grid, 256, FB_SMEM>>>(out, (const __nv_bfloat16*)x);
}

// round 14
// speedup vs baseline: 1.3611x; 1.3611x over previous
#include <cuda_runtime.h>
#include <cuda_bf16.h>
#include <cuda_fp16.h>
#include <cstdint>

// ---------------------------------------------------------------------------
// Problem dims
// ---------------------------------------------------------------------------
static constexpr int K_DIM = 4096;   // in_features
static constexpr int N_DIM = 4096;   // out_features
static constexpr int M_DIM = 16384;  // B*S

// Canonical bf16 buffers (GEMM inputs), independent of input storage dtypes.
__device__ __nv_bfloat16 g_w[(size_t)N_DIM * K_DIM];   // 32 MB  [N, K]
__device__ __nv_bfloat16 g_x[(size_t)M_DIM * K_DIM];   // 128 MB [M, K]

// Runtime dtype-detection flags (deterministic given fixed inputs).
__device__ int g_q_is_i8;    // 1 if q stored as int8,  0 if int32
__device__ int g_sc_is_f16;  // 1 if scale stored fp16, 0 if fp32
__device__ int g_x_is_f32;   // 1 if x stored fp32,     0 if bf16

// ---------------------------------------------------------------------------
// Probe: detect storage dtypes by bit-pattern inspection (deterministic).
// ---------------------------------------------------------------------------
__global__ void probe_kernel(const int* __restrict__ q, const float* __restrict__ sc,
                             const unsigned* __restrict__ x) {
    __shared__ int bad_q, ok_s, ok_x;
    int tid = threadIdx.x;
    if (tid == 0) { bad_q = 0; ok_s = 0; ok_x = 0; }
    __syncthreads();

    int bq = 0;
#pragma unroll
    for (int j = 0; j < 4; j++) {
        int v = q[tid * 4 + j];
        if (v > 31 || v < -31) bq++;
    }

    float s = sc[tid];
    int os = (s > 1e-5f && s < 1.0f) ? 1 : 0;

    int ox = 0;
#pragma unroll
    for (int j = 0; j < 16; j++) {
        unsigned w = x[(size_t)(tid * 16 + j) * 131];
        unsigned e = (w >> 7) & 0xFF;
        if (e >= 105 && e <= 132) ox++;
    }

    atomicAdd(&bad_q, bq);
    atomicAdd(&ok_s, os);
    atomicAdd(&ok_x, ox);
    __syncthreads();
    if (tid == 0) {
        g_q_is_i8   = (bad_q > 0) ? 1 : 0;
        g_sc_is_f16 = (ok_s < 200) ? 1 : 0;
        g_x_is_f32  = (ok_x < 2048) ? 1 : 0;
    }
}

// ---------------------------------------------------------------------------
// Dequant: w[n,k] = bf16(float(q[n,k]) * float(scale[n]))  (reference rounding)
// ---------------------------------------------------------------------------
__global__ void dequant_kernel(const void* __restrict__ qv, const void* __restrict__ scv) {
    size_t idx = ((size_t)blockIdx.x * blockDim.x + threadIdx.x) * 8;
    int row = (int)(idx >> 12);  // /4096
    float s;
    if (g_sc_is_f16) s = __half2float(((const __half*)scv)[row]);
    else             s = ((const float*)scv)[row];

    int v[8];
    if (g_q_is_i8) {
        int2 w = *reinterpret_cast<const int2*>((const int8_t*)qv + idx);
        const int8_t* b = reinterpret_cast<const int8_t*>(&w);
#pragma unroll
        for (int i = 0; i < 8; i++) v[i] = (int)b[i];
    } else {
        const int4* p = reinterpret_cast<const int4*>((const int*)qv + idx);
        int4 a = p[0], b2 = p[1];
        v[0] = a.x; v[1] = a.y; v[2] = a.z; v[3] = a.w;
        v[4] = b2.x; v[5] = b2.y; v[6] = b2.z; v[7] = b2.w;
    }
    __nv_bfloat16 o[8];
#pragma unroll
    for (int i = 0; i < 8; i++) o[i] = __float2bfloat16(s * (float)v[i]);
    *reinterpret_cast<uint4*>(&g_w[idx]) = *reinterpret_cast<const uint4*>(o);
}

// ---------------------------------------------------------------------------
// Canonicalize x to bf16 (used only when x arrives fp32-widened).
// ---------------------------------------------------------------------------
__global__ void convert_x_kernel(const void* __restrict__ xv) {
    size_t idx = ((size_t)blockIdx.x * blockDim.x + threadIdx.x) * 8;
    if (g_x_is_f32) {
        const float4* p = reinterpret_cast<const float4*>((const float*)xv + idx);
        float4 a = p[0], b = p[1];
        __nv_bfloat16 o[8];
        o[0] = __float2bfloat16(a.x); o[1] = __float2bfloat16(a.y);
        o[2] = __float2bfloat16(a.z); o[3] = __float2bfloat16(a.w);
        o[4] = __float2bfloat16(b.x); o[5] = __float2bfloat16(b.y);
        o[6] = __float2bfloat16(b.z); o[7] = __float2bfloat16(b.w);
        *reinterpret_cast<uint4*>(&g_x[idx]) = *reinterpret_cast<const uint4*>(o);
    }
}

// ===========================================================================
// Tensor-core GEMM via mma.sync. CTA 128x128x32, 8 warps (4m x 2n),
// 5-stage cp.async pipeline (wait_group 3), ONE barrier per K-step, next
// loads issued BETWEEN the two ki half-steps so MMAs start immediately
// after the barrier. 80B-padded rows -> conflict-free ldmatrix.
// Output: f32(bf16(f32_accum)) stored as FLOAT32.
// ===========================================================================
static constexpr int FB_BM = 128;
static constexpr int FB_BN = 128;
static constexpr int FB_BK = 32;
static constexpr int FB_KT = K_DIM / FB_BK;                 // 128
static constexpr int FB_STRIDE = 40;                        // elems per row (80B)
static constexpr int FB_TILE_BYTES = 128 * FB_STRIDE * 2;   // 10240
static constexpr int FB_STAGE_BYTES = 2 * FB_TILE_BYTES;    // 20480
static constexpr int FB_STAGES = 5;
static constexpr int FB_SMEM = FB_STAGES * FB_STAGE_BYTES;  // 102400 -> 2 CTAs/SM

__device__ __forceinline__ uint32_t smem_to_u32(const void* p) {
    uint32_t a;
    asm("{ .reg .u64 t; cvta.to.shared.u64 t, %1; cvt.u32.u64 %0, t; }" : "=r"(a) : "l"(p));
    return a;
}

#define CP_ASYNC_16(smem, gmem) \
    asm volatile("cp.async.cg.shared.global [%0], [%1], 16;" :: "r"((uint32_t)(smem)), "l"(gmem) : "memory")
#define CP_COMMIT() asm volatile("cp.async.commit_group;" ::: "memory")
#define CP_WAIT_GROUP(n) asm volatile("cp.async.wait_group %0;" :: "n"(n) : "memory")

#define LDMATRIX_X4(r0, r1, r2, r3, addr) \
    asm volatile("ldmatrix.sync.aligned.m8n8.x4.shared.b16 {%0,%1,%2,%3}, [%4];" \
        : "=r"(r0), "=r"(r1), "=r"(r2), "=r"(r3) : "r"(addr))

#define MMA_16816_BF16(d, a, b) \
    asm volatile("mma.sync.aligned.m16n8k16.row.col.f32.bf16.bf16.f32 " \
        "{%0,%1,%2,%3}, {%4,%5,%6,%7}, {%8,%9}, {%0,%1,%2,%3};" \
        : "+f"((d)[0]), "+f"((d)[1]), "+f"((d)[2]), "+f"((d)[3]) \
        : "r"((a)[0]), "r"((a)[1]), "r"((a)[2]), "r"((a)[3]), "r"((b)[0]), "r"((b)[1]))

__device__ __forceinline__ void fb_load_stage(const __nv_bfloat16* __restrict__ xsrc,
                                              int m0, int n0, int k0,
                                              uint32_t stage_smem, int tid) {
    uint32_t a_base = stage_smem;
#pragma unroll
    for (int i = 0; i < 2; i++) {
        int idx = tid + i * 256;
        int r = idx >> 2, c = idx & 3;
        uint32_t off = (uint32_t)(r * (FB_STRIDE * 2) + c * 16);
        const void* g = (const void*)(xsrc + (size_t)(m0 + r) * K_DIM + k0 + c * 8);
        CP_ASYNC_16(a_base + off, g);
    }
    uint32_t b_base = stage_smem + FB_TILE_BYTES;
#pragma unroll
    for (int i = 0; i < 2; i++) {
        int idx = tid + i * 256;
        int r = idx >> 2, c = idx & 3;
        uint32_t off = (uint32_t)(r * (FB_STRIDE * 2) + c * 16);
        const void* g = (const void*)(g_w + (size_t)(n0 + r) * K_DIM + k0 + c * 8);
        CP_ASYNC_16(b_base + off, g);
    }
}

__global__ void __launch_bounds__(256, 2)
gemm_mma(float* __restrict__ out, const __nv_bfloat16* __restrict__ x_raw) {
    extern __shared__ char smem_raw[];
    uint32_t smem_base = smem_to_u32(smem_raw);

    int tid = threadIdx.x;
    int wid = tid >> 5;
    int lid = tid & 31;
    int warp_m = wid & 3;     // 4 warps along M
    int warp_n = wid >> 2;    // 2 warps along N

    int n_tile = blockIdx.x & 31;   // n fastest: W stays L2-hot
    int m_tile = blockIdx.x >> 5;
    int m0 = m_tile * FB_BM;
    int n0 = n_tile * FB_BN;

    const __nv_bfloat16* xsrc = g_x_is_f32 ? g_x : x_raw;

    float acc[2][8][4];
#pragma unroll
    for (int t = 0; t < 2; t++)
#pragma unroll
        for (int j = 0; j < 8; j++)
#pragma unroll
            for (int e = 0; e < 4; e++) acc[t][j][e] = 0.0f;

    // Prologue: 4 stages in flight.
#pragma unroll
    for (int s = 0; s < 4; s++) {
        fb_load_stage(xsrc, m0, n0, s * FB_BK, smem_base + (uint32_t)s * FB_STAGE_BYTES, tid);
        CP_COMMIT();
    }

    int lr = lid & 7;
    int lg = lid >> 3;

    for (int kt = 0; kt < FB_KT; ++kt) {
        CP_WAIT_GROUP(3);        // stage kt complete (4 groups pending -> 3)
        __syncthreads();         // all threads see it; frees buffer (kt-1)%5

        uint32_t stage = smem_base + (uint32_t)(kt % FB_STAGES) * FB_STAGE_BYTES;
        uint32_t a_base = stage;
        uint32_t b_base = stage + FB_TILE_BYTES;

        // ---- ki = 0: fragments + MMAs first, so tensor starts immediately
        uint32_t a_frag[2][4];
        uint32_t b_frag[8][2];
#pragma unroll
        for (int t = 0; t < 2; t++) {
            int row = warp_m * 32 + t * 16 + (lg & 1) * 8 + lr;
            int col = (lg >> 1) * 8;
            uint32_t addr = a_base + (uint32_t)(row * (FB_STRIDE * 2) + col * 2);
            LDMATRIX_X4(a_frag[t][0], a_frag[t][1], a_frag[t][2], a_frag[t][3], addr);
        }
#pragma unroll
        for (int j2 = 0; j2 < 4; j2++) {
            int nrow = warp_n * 64 + (j2 * 2 + (lg >> 1)) * 8 + lr;
            int kcol = (lg & 1) * 8;
            uint32_t addr = b_base + (uint32_t)(nrow * (FB_STRIDE * 2) + kcol * 2);
            LDMATRIX_X4(b_frag[2 * j2][0], b_frag[2 * j2][1],
                        b_frag[2 * j2 + 1][0], b_frag[2 * j2 + 1][1], addr);
        }
#pragma unroll
        for (int t = 0; t < 2; t++)
#pragma unroll
            for (int j = 0; j < 8; j++)
                MMA_16816_BF16(acc[t][j], a_frag[t], b_frag[j]);

        // ---- issue next stage's loads; they overlap ki=0 MMA tail + ki=1
        if (kt + 4 < FB_KT) {
            fb_load_stage(xsrc, m0, n0, (kt + 4) * FB_BK,
                          smem_base + (uint32_t)((kt + 4) % FB_STAGES) * FB_STAGE_BYTES, tid);
        }
        CP_COMMIT();             // uniform commit -> stable wait count

        // ---- ki = 1
#pragma unroll
        for (int t = 0; t < 2; t++) {
            int row = warp_m * 32 + t * 16 + (lg & 1) * 8 + lr;
            int col = 16 + (lg >> 1) * 8;
            uint32_t addr = a_base + (uint32_t)(row * (FB_STRIDE * 2) + col * 2);
            LDMATRIX_X4(a_frag[t][0], a_frag[t][1], a_frag[t][2], a_frag[t][3], addr);
        }
#pragma unroll
        for (int j2 = 0; j2 < 4; j2++) {
            int nrow = warp_n * 64 + (j2 * 2 + (lg >> 1)) * 8 + lr;
            int kcol = 16 + (lg & 1) * 8;
            uint32_t addr = b_base + (uint32_t)(nrow * (FB_STRIDE * 2) + kcol * 2);
            LDMATRIX_X4(b_frag[2 * j2][0], b_frag[2 * j2][1],
                        b_frag[2 * j2 + 1][0], b_frag[2 * j2 + 1][1], addr);
        }
#pragma unroll
        for (int t = 0; t < 2; t++)
#pragma unroll
            for (int j = 0; j < 8; j++)
                MMA_16816_BF16(acc[t][j], a_frag[t], b_frag[j]);
        // Buffer kt%5 is only rewritten at kt+5, ordered by that iteration's
        // top-of-loop barrier.
    }

    // Epilogue: bf16-round (reference einsum output), widen, store FP32.
    int qr = lid >> 2;
    int qc = lid & 3;
#pragma unroll
    for (int t = 0; t < 2; t++) {
#pragma unroll
        for (int j = 0; j < 8; j++) {
            size_t row0 = (size_t)m0 + warp_m * 32 + t * 16 + qr;
            size_t col = (size_t)n0 + warp_n * 64 + j * 8 + qc * 2;
            float2 v0, v1;
            v0.x = __bfloat162float(__float2bfloat16(acc[t][j][0]));
            v0.y = __bfloat162float(__float2bfloat16(acc[t][j][1]));
            v1.x = __bfloat162float(__float2bfloat16(acc[t][j][2]));
            v1.y = __bfloat162float(__float2bfloat16(acc[t][j][3]));
            *reinterpret_cast<float2*>(out + row0 * N_DIM + col) = v0;
            *reinterpret_cast<float2*>(out + (row0 + 8) * N_DIM + col) = v1;
        }
    }
}

// ---------------------------------------------------------------------------
// Launch. Inputs routed by element count; dtypes detected on-device.
// ---------------------------------------------------------------------------
extern "C" void kernel_launch(void* const* d_in, const int* in_sizes, int n_in,
                              void* d_out, int out_size) {
    const void* x = nullptr;
    const void* q = nullptr;
    const void* scale = nullptr;
    for (int i = 0; i < n_in; i++) {
        if (in_sizes[i] == M_DIM * K_DIM) x = d_in[i];
        else if (in_sizes[i] == N_DIM * K_DIM) q = d_in[i];
        else if (in_sizes[i] == N_DIM) scale = d_in[i];
    }
    float* out = (float*)d_out;

    cudaFuncSetAttribute(gemm_mma, cudaFuncAttributeMaxDynamicSharedMemorySize, FB_SMEM);

    probe_kernel<<<1, 256>>>((const int*)q, (const float*)scale, (const unsigned*)x);

    dequant_kernel<<<8192, 256>>>(q, scale);       // 16.7M / (256*8)
    convert_x_kernel<<<32768, 256>>>(x);           // no-op if x already bf16

    int grid = (M_DIM / FB_BM) * (N_DIM / FB_BN);  // 128 * 32 = 4096
    gemm_mma<<<grid, 256, FB_SMEM>>>(out, (const __nv_bfloat16*)x);
}

// round 16
// speedup vs baseline: 1.4655x; 1.0767x over previous
#include <cuda_runtime.h>
#include <cuda_bf16.h>
#include <cuda_fp16.h>
#include <cstdint>

// ---------------------------------------------------------------------------
// Problem dims
// ---------------------------------------------------------------------------
static constexpr int K_DIM = 4096;   // in_features
static constexpr int N_DIM = 4096;   // out_features
static constexpr int M_DIM = 16384;  // B*S

// Canonical bf16 buffers (GEMM inputs), independent of input storage dtypes.
__device__ __nv_bfloat16 g_w[(size_t)N_DIM * K_DIM];   // 32 MB  [N, K]
__device__ __nv_bfloat16 g_x[(size_t)M_DIM * K_DIM];   // 128 MB [M, K]

// Runtime dtype-detection flags (deterministic given fixed inputs).
__device__ int g_q_is_i8;    // 1 if q stored as int8,  0 if int32
__device__ int g_sc_is_f16;  // 1 if scale stored fp16, 0 if fp32
__device__ int g_x_is_f32;   // 1 if x stored fp32,     0 if bf16

// ---------------------------------------------------------------------------
// Probe: detect storage dtypes by bit-pattern inspection (deterministic).
// ---------------------------------------------------------------------------
__global__ void probe_kernel(const int* __restrict__ q, const float* __restrict__ sc,
                             const unsigned* __restrict__ x) {
    __shared__ int bad_q, ok_s, ok_x;
    int tid = threadIdx.x;
    if (tid == 0) { bad_q = 0; ok_s = 0; ok_x = 0; }
    __syncthreads();

    int bq = 0;
#pragma unroll
    for (int j = 0; j < 4; j++) {
        int v = q[tid * 4 + j];
        if (v > 31 || v < -31) bq++;
    }

    float s = sc[tid];
    int os = (s > 1e-5f && s < 1.0f) ? 1 : 0;

    int ox = 0;
#pragma unroll
    for (int j = 0; j < 16; j++) {
        unsigned w = x[(size_t)(tid * 16 + j) * 131];
        unsigned e = (w >> 7) & 0xFF;
        if (e >= 105 && e <= 132) ox++;
    }

    atomicAdd(&bad_q, bq);
    atomicAdd(&ok_s, os);
    atomicAdd(&ok_x, ox);
    __syncthreads();
    if (tid == 0) {
        g_q_is_i8   = (bad_q > 0) ? 1 : 0;
        g_sc_is_f16 = (ok_s < 200) ? 1 : 0;
        g_x_is_f32  = (ok_x < 2048) ? 1 : 0;
    }
}

// ---------------------------------------------------------------------------
// Dequant: w[n,k] = bf16(float(q[n,k]) * float(scale[n]))  (reference rounding)
// ---------------------------------------------------------------------------
__global__ void dequant_kernel(const void* __restrict__ qv, const void* __restrict__ scv) {
    size_t idx = ((size_t)blockIdx.x * blockDim.x + threadIdx.x) * 8;
    int row = (int)(idx >> 12);  // /4096
    float s;
    if (g_sc_is_f16) s = __half2float(((const __half*)scv)[row]);
    else             s = ((const float*)scv)[row];

    int v[8];
    if (g_q_is_i8) {
        int2 w = *reinterpret_cast<const int2*>((const int8_t*)qv + idx);
        const int8_t* b = reinterpret_cast<const int8_t*>(&w);
#pragma unroll
        for (int i = 0; i < 8; i++) v[i] = (int)b[i];
    } else {
        const int4* p = reinterpret_cast<const int4*>((const int*)qv + idx);
        int4 a = p[0], b2 = p[1];
        v[0] = a.x; v[1] = a.y; v[2] = a.z; v[3] = a.w;
        v[4] = b2.x; v[5] = b2.y; v[6] = b2.z; v[7] = b2.w;
    }
    __nv_bfloat16 o[8];
#pragma unroll
    for (int i = 0; i < 8; i++) o[i] = __float2bfloat16(s * (float)v[i]);
    *reinterpret_cast<uint4*>(&g_w[idx]) = *reinterpret_cast<const uint4*>(o);
}

// ---------------------------------------------------------------------------
// Canonicalize x to bf16 (used only when x arrives fp32-widened).
// ---------------------------------------------------------------------------
__global__ void convert_x_kernel(const void* __restrict__ xv) {
    size_t idx = ((size_t)blockIdx.x * blockDim.x + threadIdx.x) * 8;
    if (g_x_is_f32) {
        const float4* p = reinterpret_cast<const float4*>((const float*)xv + idx);
        float4 a = p[0], b = p[1];
        __nv_bfloat16 o[8];
        o[0] = __float2bfloat16(a.x); o[1] = __float2bfloat16(a.y);
        o[2] = __float2bfloat16(a.z); o[3] = __float2bfloat16(a.w);
        o[4] = __float2bfloat16(b.x); o[5] = __float2bfloat16(b.y);
        o[6] = __float2bfloat16(b.z); o[7] = __float2bfloat16(b.w);
        *reinterpret_cast<uint4*>(&g_x[idx]) = *reinterpret_cast<const uint4*>(o);
    }
}

// ===========================================================================
// Tensor-core GEMM via mma.sync. CTA 128x128x64, 8 warps (4m x 2n),
// 3-stage cp.async pipeline (wait_group 1), ONE barrier per 64-K step
// (64 MMAs/warp between barriers), next loads issued after ki=0.
// 144B-padded rows -> conflict-free ldmatrix (row step = 4 banks).
// Output: f32(bf16(f32_accum)) stored as FLOAT32.
// ===========================================================================
static constexpr int FB_BM = 128;
static constexpr int FB_BN = 128;
static constexpr int FB_BK = 64;
static constexpr int FB_KT = K_DIM / FB_BK;                 // 64
static constexpr int FB_STRIDE = 72;                        // elems per row (144B)
static constexpr int FB_TILE_BYTES = 128 * FB_STRIDE * 2;   // 18432
static constexpr int FB_STAGE_BYTES = 2 * FB_TILE_BYTES;    // 36864
static constexpr int FB_STAGES = 3;
static constexpr int FB_SMEM = FB_STAGES * FB_STAGE_BYTES;  // 110592 -> 2 CTAs/SM

__device__ __forceinline__ uint32_t smem_to_u32(const void* p) {
    uint32_t a;
    asm("{ .reg .u64 t; cvta.to.shared.u64 t, %1; cvt.u32.u64 %0, t; }" : "=r"(a) : "l"(p));
    return a;
}

#define CP_ASYNC_16(smem, gmem) \
    asm volatile("cp.async.cg.shared.global [%0], [%1], 16;" :: "r"((uint32_t)(smem)), "l"(gmem) : "memory")
#define CP_COMMIT() asm volatile("cp.async.commit_group;" ::: "memory")
#define CP_WAIT_GROUP(n) asm volatile("cp.async.wait_group %0;" :: "n"(n) : "memory")

#define LDMATRIX_X4(r0, r1, r2, r3, addr) \
    asm volatile("ldmatrix.sync.aligned.m8n8.x4.shared.b16 {%0,%1,%2,%3}, [%4];" \
        : "=r"(r0), "=r"(r1), "=r"(r2), "=r"(r3) : "r"(addr))

#define MMA_16816_BF16(d, a, b) \
    asm volatile("mma.sync.aligned.m16n8k16.row.col.f32.bf16.bf16.f32 " \
        "{%0,%1,%2,%3}, {%4,%5,%6,%7}, {%8,%9}, {%0,%1,%2,%3};" \
        : "+f"((d)[0]), "+f"((d)[1]), "+f"((d)[2]), "+f"((d)[3]) \
        : "r"((a)[0]), "r"((a)[1]), "r"((a)[2]), "r"((a)[3]), "r"((b)[0]), "r"((b)[1]))

__device__ __forceinline__ void fb_load_stage(const __nv_bfloat16* __restrict__ xsrc,
                                              int m0, int n0, int k0,
                                              uint32_t stage_smem, int tid) {
    // A: 128 rows x 8 chunks(16B) = 1024; 256 threads -> 4 each.
    uint32_t a_base = stage_smem;
#pragma unroll
    for (int i = 0; i < 4; i++) {
        int idx = tid + i * 256;
        int r = idx >> 3, c = idx & 7;
        uint32_t off = (uint32_t)(r * (FB_STRIDE * 2) + c * 16);
        const void* g = (const void*)(xsrc + (size_t)(m0 + r) * K_DIM + k0 + c * 8);
        CP_ASYNC_16(a_base + off, g);
    }
    // B: same shape.
    uint32_t b_base = stage_smem + FB_TILE_BYTES;
#pragma unroll
    for (int i = 0; i < 4; i++) {
        int idx = tid + i * 256;
        int r = idx >> 3, c = idx & 7;
        uint32_t off = (uint32_t)(r * (FB_STRIDE * 2) + c * 16);
        const void* g = (const void*)(g_w + (size_t)(n0 + r) * K_DIM + k0 + c * 8);
        CP_ASYNC_16(b_base + off, g);
    }
}

__global__ void __launch_bounds__(256, 2)
gemm_mma(float* __restrict__ out, const __nv_bfloat16* __restrict__ x_raw) {
    extern __shared__ char smem_raw[];
    uint32_t smem_base = smem_to_u32(smem_raw);

    int tid = threadIdx.x;
    int wid = tid >> 5;
    int lid = tid & 31;
    int warp_m = wid & 3;     // 4 warps along M
    int warp_n = wid >> 2;    // 2 warps along N

    int n_tile = blockIdx.x & 31;   // n fastest: W stays L2-hot
    int m_tile = blockIdx.x >> 5;
    int m0 = m_tile * FB_BM;
    int n0 = n_tile * FB_BN;

    const __nv_bfloat16* xsrc = g_x_is_f32 ? g_x : x_raw;

    float acc[2][8][4];
#pragma unroll
    for (int t = 0; t < 2; t++)
#pragma unroll
        for (int j = 0; j < 8; j++)
#pragma unroll
            for (int e = 0; e < 4; e++) acc[t][j][e] = 0.0f;

    // Prologue: 2 stages in flight.
    fb_load_stage(xsrc, m0, n0, 0 * FB_BK, smem_base + 0 * FB_STAGE_BYTES, tid);
    CP_COMMIT();
    fb_load_stage(xsrc, m0, n0, 1 * FB_BK, smem_base + 1 * FB_STAGE_BYTES, tid);
    CP_COMMIT();

    int lr = lid & 7;
    int lg = lid >> 3;

    for (int kt = 0; kt < FB_KT; ++kt) {
        CP_WAIT_GROUP(1);        // stage kt's loads complete
        __syncthreads();         // all threads; also frees buffer (kt-1)%3

        uint32_t stage = smem_base + (uint32_t)(kt % FB_STAGES) * FB_STAGE_BYTES;
        uint32_t a_base = stage;
        uint32_t b_base = stage + FB_TILE_BYTES;

        uint32_t a_frag[2][4];
        uint32_t b_frag[8][2];

        // ---- ki = 0 first: tensor pipe starts immediately after barrier.
#pragma unroll
        for (int t = 0; t < 2; t++) {
            int row = warp_m * 32 + t * 16 + (lg & 1) * 8 + lr;
            int col = (lg >> 1) * 8;
            uint32_t addr = a_base + (uint32_t)(row * (FB_STRIDE * 2) + col * 2);
            LDMATRIX_X4(a_frag[t][0], a_frag[t][1], a_frag[t][2], a_frag[t][3], addr);
        }
#pragma unroll
        for (int j2 = 0; j2 < 4; j2++) {
            int nrow = warp_n * 64 + (j2 * 2 + (lg >> 1)) * 8 + lr;
            int kcol = (lg & 1) * 8;
            uint32_t addr = b_base + (uint32_t)(nrow * (FB_STRIDE * 2) + kcol * 2);
            LDMATRIX_X4(b_frag[2 * j2][0], b_frag[2 * j2][1],
                        b_frag[2 * j2 + 1][0], b_frag[2 * j2 + 1][1], addr);
        }
#pragma unroll
        for (int t = 0; t < 2; t++)
#pragma unroll
            for (int j = 0; j < 8; j++)
                MMA_16816_BF16(acc[t][j], a_frag[t], b_frag[j]);

        // ---- issue next stage's loads; overlap ki=1..3 compute.
        if (kt + 2 < FB_KT) {
            fb_load_stage(xsrc, m0, n0, (kt + 2) * FB_BK,
                          smem_base + (uint32_t)((kt + 2) % FB_STAGES) * FB_STAGE_BYTES, tid);
        }
        CP_COMMIT();             // uniform commit -> stable wait count

        // ---- ki = 1..3
#pragma unroll
        for (int ki = 1; ki < 4; ki++) {
#pragma unroll
            for (int t = 0; t < 2; t++) {
                int row = warp_m * 32 + t * 16 + (lg & 1) * 8 + lr;
                int col = ki * 16 + (lg >> 1) * 8;
                uint32_t addr = a_base + (uint32_t)(row * (FB_STRIDE * 2) + col * 2);
                LDMATRIX_X4(a_frag[t][0], a_frag[t][1], a_frag[t][2], a_frag[t][3], addr);
            }
#pragma unroll
            for (int j2 = 0; j2 < 4; j2++) {
                int nrow = warp_n * 64 + (j2 * 2 + (lg >> 1)) * 8 + lr;
                int kcol = ki * 16 + (lg & 1) * 8;
                uint32_t addr = b_base + (uint32_t)(nrow * (FB_STRIDE * 2) + kcol * 2);
                LDMATRIX_X4(b_frag[2 * j2][0], b_frag[2 * j2][1],
                            b_frag[2 * j2 + 1][0], b_frag[2 * j2 + 1][1], addr);
            }
#pragma unroll
            for (int t = 0; t < 2; t++)
#pragma unroll
                for (int j = 0; j < 8; j++)
                    MMA_16816_BF16(acc[t][j], a_frag[t], b_frag[j]);
        }
        // Buffer kt%3 is only rewritten at kt+3, ordered by that iteration's
        // top-of-loop barrier.
    }

    // Epilogue: bf16-round (reference einsum output), widen, store FP32.
    int qr = lid >> 2;
    int qc = lid & 3;
#pragma unroll
    for (int t = 0; t < 2; t++) {
#pragma unroll
        for (int j = 0; j < 8; j++) {
            size_t row0 = (size_t)m0 + warp_m * 32 + t * 16 + qr;
            size_t col = (size_t)n0 + warp_n * 64 + j * 8 + qc * 2;
            float2 v0, v1;
            v0.x = __bfloat162float(__float2bfloat16(acc[t][j][0]));
            v0.y = __bfloat162float(__float2bfloat16(acc[t][j][1]));
            v1.x = __bfloat162float(__float2bfloat16(acc[t][j][2]));
            v1.y = __bfloat162float(__float2bfloat16(acc[t][j][3]));
            *reinterpret_cast<float2*>(out + row0 * N_DIM + col) = v0;
            *reinterpret_cast<float2*>(out + (row0 + 8) * N_DIM + col) = v1;
        }
    }
}

// ---------------------------------------------------------------------------
// Launch. Inputs routed by element count; dtypes detected on-device.
// ---------------------------------------------------------------------------
extern "C" void kernel_launch(void* const* d_in, const int* in_sizes, int n_in,
                              void* d_out, int out_size) {
    const void* x = nullptr;
    const void* q = nullptr;
    const void* scale = nullptr;
    for (int i = 0; i < n_in; i++) {
        if (in_sizes[i] == M_DIM * K_DIM) x = d_in[i];
        else if (in_sizes[i] == N_DIM * K_DIM) q = d_in[i];
        else if (in_sizes[i] == N_DIM) scale = d_in[i];
    }
    float* out = (float*)d_out;

    cudaFuncSetAttribute(gemm_mma, cudaFuncAttributeMaxDynamicSharedMemorySize, FB_SMEM);

    probe_kernel<<<1, 256>>>((const int*)q, (const float*)scale, (const unsigned*)x);

    dequant_kernel<<<8192, 256>>>(q, scale);       // 16.7M / (256*8)
    convert_x_kernel<<<32768, 256>>>(x);           // no-op if x already bf16

    int grid = (M_DIM / FB_BM) * (N_DIM / FB_BN);  // 128 * 32 = 4096
    gemm_mma<<<grid, 256, FB_SMEM>>>(out, (const __nv_bfloat16*)x);
}